// round 11
// baseline (speedup 1.0000x reference)
#include <cuda_runtime.h>
#include <math.h>

// Van Rossum distance — split-row blocked scan, occupancy-doubled.
//   diff = input - target            [1024, 16384] f32
//   y[t] = d*y[t-1] + diff[t]        d = exp(-1/20), per row
//   out  = sqrt( sum(y^2) / 20 )     scalar f32
//
// R11: 2048 blocks (2 per row, 8192 elems each), 128 threads, regs capped
// via __launch_bounds__(128,14) -> 14 blocks/SM -> 56 warps/SM resident
// (R10 was grid-limited at 27.7). Blocks need no sequential carry: each
// exports (A, B, T) for its half-row; merge uses A0+A1+2*T0*B1+T0^2*C.
// Inner algebra identical to the validated R8 geometry (SEG=2048, ITERS=16).

#define LEN      16384
#define NROWS    1024
#define THREADS  128
#define NWARPS   4
#define HALVES   2
#define NBLOCKS  (NROWS * HALVES)   // 2048
#define HALFLEN  (LEN / HALVES)     // 8192
#define SEG      (HALFLEN / NWARPS) // 2048 elements per warp
#define ITERS    (SEG / 128)        // 16 iterations of 128 (32 lanes x 4)

__device__ float        g_A[NBLOCKS];   // half-row sum(y^2), zero carry-in
__device__ float        g_B[NBLOCKS];   // half-row B-moment
__device__ float        g_T[NBLOCKS];   // half-row final scan value
__device__ unsigned int g_ticket = 0;

__global__ __launch_bounds__(THREADS, 14) void vr_kernel(
    const float* __restrict__ inp, const float* __restrict__ tgt,
    float* __restrict__ out)
{
    __shared__ float warpA[NWARPS];
    __shared__ float warpB[NWARPS];
    __shared__ float warpT[NWARPS];
    __shared__ float wsum[NWARPS];
    __shared__ bool  isLast;

    const int bid  = blockIdx.x;
    const int row  = bid >> 1;
    const int half = bid & 1;
    const int tid  = threadIdx.x;
    const int lane = tid & 31;
    const int warp = tid >> 5;

    // ---- constants ----
    const float d   = 0.951229424500714f;          // exp(-1/20)
    const float d2  = d * d;
    const float D4  = d2 * d2;                     // d^4
    float D128 = D4;                               // d^128 via 5 squarings
    #pragma unroll
    for (int i = 0; i < 5; i++) D128 = D128 * D128;
    float D2048 = D128;                            // d^2048 (~4e-45, eff. 0)
    #pragma unroll
    for (int i = 0; i < 4; i++) D2048 = D2048 * D2048;
    const float C4   = d2 * (1.0f - D4 * D4) / (1.0f - d2);      // sum d^2k, k=1..4
    const float C128 = d2 * (1.0f - D128 * D128) / (1.0f - d2);  // k=1..128
    const float CBIG = d2 / (1.0f - d2);                         // k=1..inf tail ~ L>=2048
    // Dl4 = d^(4*lane)
    float Dl4 = 1.0f, bsq = D4;
    #pragma unroll
    for (int b = 0; b < 5; b++) {
        if (lane & (1 << b)) Dl4 *= bsq;
        bsq *= bsq;
    }

    const size_t base = (size_t)row * LEN + (size_t)half * HALFLEN;
    const float4* __restrict__ ip =
        (const float4*)(inp + base) + warp * (SEG / 4) + lane;
    const float4* __restrict__ tp =
        (const float4*)(tgt + base) + warp * (SEG / 4) + lane;

    float contrib = 0.0f;   // sum y^2 share (within-segment carries folded)
    float BwAcc   = 0.0f;   // per-lane part of segment B-moment
    float W       = 0.0f;   // sum_j K_j * c_j     (uniform across warp)
    float cj      = 0.0f;   // carry into iteration j (uniform across warp)
    float K       = 1.0f;   // d^(128*j)           (uniform across warp)
    float KD      = Dl4;    // K * d^(4*lane)

    // depth-1 prefetch
    float4 a = ip[0];
    float4 b = tp[0];

    #pragma unroll
    for (int j = 0; j < ITERS; j++) {
        float4 an, bn;
        if (j + 1 < ITERS) {
            an = ip[(j + 1) * 32];
            bn = tp[(j + 1) * 32];
        }

        float x0 = a.x - b.x, x1 = a.y - b.y, x2 = a.z - b.z, x3 = a.w - b.w;

        // local 4-scan, zero carry-in
        float y0 = x0;
        float y1 = fmaf(d, y0, x1);
        float y2 = fmaf(d, y1, x2);
        float y3 = fmaf(d, y2, x3);

        // A_t = sum y^2 ; B_t = y0 d + y1 d^2 + y2 d^3 + y3 d^4 (Horner)
        float At = fmaf(y3, y3, fmaf(y2, y2, fmaf(y1, y1, y0 * y0)));
        float Bt = d * fmaf(d, fmaf(d, fmaf(d, y3, y2), y1), y0);

        // warp inclusive scan of chunk totals, weight D4
        float sI = y3;
        float w  = D4;
        #pragma unroll
        for (int off = 1; off < 32; off <<= 1) {
            float up = __shfl_up_sync(0xffffffffu, sI, off);
            if (lane >= off) sI = fmaf(w, up, sI);
            w *= w;
        }
        float E = __shfl_up_sync(0xffffffffu, sI, 1);
        if (lane == 0) E = 0.0f;

        // true carry into this thread's chunk
        float c = fmaf(cj, Dl4, E);

        // chunk contribution: At + 2cBt + c^2 C4
        contrib += fmaf(c, fmaf(c, C4, Bt + Bt), At);

        // segment B-moment: KD * (Bt + E*C4)
        BwAcc = fmaf(KD, fmaf(E, C4, Bt), BwAcc);
        W     = fmaf(K, cj, W);

        // serial iteration-carry update
        float Tj = __shfl_sync(0xffffffffu, sI, 31);
        cj = fmaf(D128, cj, Tj);
        K  *= D128;
        KD *= D128;

        a = an;
        b = bn;
    }

    // ---- per-warp reduce of contrib and BwAcc ----
    #pragma unroll
    for (int off = 16; off > 0; off >>= 1) {
        contrib += __shfl_down_sync(0xffffffffu, contrib, off);
        BwAcc   += __shfl_down_sync(0xffffffffu, BwAcc, off);
    }
    if (lane == 0) {
        warpA[warp] = contrib;
        warpB[warp] = fmaf(C128, W, BwAcc);  // + carry-induced B terms
        warpT[warp] = cj;                    // segment-final value
    }
    __syncthreads();

    // ---- tid0: chain warp segments -> half-row (A, B, T) ----
    if (tid == 0) {
        float g = 0.0f, tot = 0.0f, Bb = 0.0f, Kv = 1.0f;
        #pragma unroll
        for (int v = 0; v < NWARPS; v++) {
            tot += fmaf(g, fmaf(g, CBIG, 2.0f * warpB[v]), warpA[v]);
            Bb   = fmaf(Kv, fmaf(g, CBIG, warpB[v]), Bb);
            g    = fmaf(D2048, g, warpT[v]);
            Kv  *= D2048;
        }
        g_A[bid] = tot;
        g_B[bid] = Bb;
        g_T[bid] = g;
        __threadfence();
        unsigned int t = atomicAdd(&g_ticket, 1u);
        isLast = (t == NBLOCKS - 1);
    }
    __syncthreads();

    // ---- last block: merge half-rows + fixed-order global reduce ----
    if (isLast) {
        __threadfence();
        float v = 0.0f;
        #pragma unroll
        for (int j = 0; j < NROWS / THREADS; j++) {
            const int i  = tid + j * THREADS;     // row index
            float A0 = ((volatile float*)g_A)[2 * i];
            float A1 = ((volatile float*)g_A)[2 * i + 1];
            float B1 = ((volatile float*)g_B)[2 * i + 1];
            float T0 = ((volatile float*)g_T)[2 * i];
            // row total = A0 + A1 + 2*T0*B1 + T0^2*CBIG
            v += A0 + fmaf(T0, fmaf(T0, CBIG, 2.0f * B1), A1);
        }

        #pragma unroll
        for (int off = 16; off > 0; off >>= 1)
            v += __shfl_down_sync(0xffffffffu, v, off);
        if (lane == 0) wsum[warp] = v;
        __syncthreads();
        if (warp == 0) {
            float t2 = (lane < NWARPS) ? wsum[lane] : 0.0f;
            #pragma unroll
            for (int off = 2; off > 0; off >>= 1)
                t2 += __shfl_down_sync(0xffffffffu, t2, off);
            if (lane == 0) {
                out[0] = sqrtf(t2 * 0.05f);   // sqrt(sum / TAU * DT)
                g_ticket = 0;                 // reset for next graph replay
            }
        }
    }
}

extern "C" void kernel_launch(void* const* d_in, const int* in_sizes, int n_in,
                              void* d_out, int out_size)
{
    const float* inp = (const float*)d_in[0];
    const float* tgt = (const float*)d_in[1];
    float* out = (float*)d_out;

    vr_kernel<<<NBLOCKS, THREADS>>>(inp, tgt, out);
}

// round 15
// speedup vs baseline: 1.0792x; 1.0792x over previous
#include <cuda_runtime.h>
#include <cuda_pipeline_primitives.h>
#include <math.h>

// Van Rossum distance — cp.async ring (pipeline intrinsics), barrier-free
// warp-autonomous scan.
//   diff = input - target            [1024, 16384] f32
//   y[t] = d*y[t-1] + diff[t]        d = exp(-1/20), per row
//   out  = sqrt( sum(y^2) / 20 )     scalar f32
//
// R14 = R12 algorithm with official pipeline intrinsics instead of raw PTX:
// loads go through cp.async (LDGSTS) into a per-warp smem ring (6 stages x
// 1KB), decoupling load issue from the shuffle-scan dependency chain that
// limited per-warp MLP to ~2 LDG (R10 prefetch and R11 occupancy both
// proved neutral at DRAM ~57%). Each lane consumes only bytes it copied
// itself, so __pipeline_wait_prior is the only main-loop synchronization.
// Scan algebra identical to validated R9 (SEG=4096, ITERS=32).

#define LEN      16384
#define NROWS    1024
#define THREADS  128
#define NWARPS   4
#define SEG      (LEN / NWARPS)     // 4096 elements per warp
#define ITERS    (SEG / 128)        // 32 iterations of 128 (32 lanes x 4)
#define STAGES   6                  // ring depth: 6 KB in flight per warp
#define STAGE_F4 64                 // float4 slots per stage (32 ip + 32 tgt)

__device__ float        g_partials[NROWS];
__device__ unsigned int g_ticket = 0;

__global__ __launch_bounds__(THREADS) void vr_kernel(
    const float* __restrict__ inp, const float* __restrict__ tgt,
    float* __restrict__ out)
{
    __shared__ __align__(16) float4 ring[NWARPS][STAGES][STAGE_F4];  // 24 KB
    __shared__ float warpA[NWARPS];
    __shared__ float warpB[NWARPS];
    __shared__ float warpT[NWARPS];
    __shared__ float wsum[NWARPS];
    __shared__ bool  isLast;

    const int row  = blockIdx.x;
    const int tid  = threadIdx.x;
    const int lane = tid & 31;
    const int warp = tid >> 5;

    // ---- constants ----
    const float d   = 0.951229424500714f;          // exp(-1/20)
    const float d2  = d * d;
    const float D4  = d2 * d2;                     // d^4
    float D128 = D4;                               // d^128 via 5 squarings
    #pragma unroll
    for (int i = 0; i < 5; i++) D128 = D128 * D128;
    float D4096 = D128;                            // d^4096 -> 0
    #pragma unroll
    for (int i = 0; i < 5; i++) D4096 = D4096 * D4096;
    const float C4   = d2 * (1.0f - D4 * D4) / (1.0f - d2);      // sum d^2k, k=1..4
    const float C128 = d2 * (1.0f - D128 * D128) / (1.0f - d2);  // k=1..128
    const float CBIG = d2 / (1.0f - d2);                         // k=1..4096 (tail=0)
    // Dl4 = d^(4*lane)
    float Dl4 = 1.0f, bsq = D4;
    #pragma unroll
    for (int b = 0; b < 5; b++) {
        if (lane & (1 << b)) Dl4 *= bsq;
        bsq *= bsq;
    }

    const float4* __restrict__ ip =
        (const float4*)(inp + (size_t)row * LEN) + warp * (SEG / 4) + lane;
    const float4* __restrict__ tp =
        (const float4*)(tgt + (size_t)row * LEN) + warp * (SEG / 4) + lane;

    // ---- prologue: fill the ring (one commit group per stage) ----
    #pragma unroll
    for (int s = 0; s < STAGES; s++) {
        __pipeline_memcpy_async(&ring[warp][s][lane],      ip + s * 32, 16);
        __pipeline_memcpy_async(&ring[warp][s][32 + lane], tp + s * 32, 16);
        __pipeline_commit();
    }

    float contrib = 0.0f;   // sum y^2 share (within-segment carries folded)
    float BwAcc   = 0.0f;   // per-lane part of segment B-moment
    float W       = 0.0f;   // sum_j K_j * c_j     (uniform across warp)
    float cj      = 0.0f;   // carry into iteration j (uniform across warp)
    float K       = 1.0f;   // d^(128*j)           (uniform across warp)
    float KD      = Dl4;    // K * d^(4*lane)

    #pragma unroll
    for (int j = 0; j < ITERS; j++) {
        const int slot = j % STAGES;

        // complete stage j's group (up to STAGES-1 newer groups stay pending)
        __pipeline_wait_prior(STAGES - 1);

        // each lane reads exactly the 32 bytes it copied itself
        float4 a = ring[warp][slot][lane];
        float4 b = ring[warp][slot][32 + lane];

        // refill this slot with stage j+STAGES (reads above already consumed it)
        if (j + STAGES < ITERS) {
            __pipeline_memcpy_async(&ring[warp][slot][lane],      ip + (j + STAGES) * 32, 16);
            __pipeline_memcpy_async(&ring[warp][slot][32 + lane], tp + (j + STAGES) * 32, 16);
        }
        __pipeline_commit();   // commit every iteration (empty group ok)

        float x0 = a.x - b.x, x1 = a.y - b.y, x2 = a.z - b.z, x3 = a.w - b.w;

        // local 4-scan, zero carry-in
        float y0 = x0;
        float y1 = fmaf(d, y0, x1);
        float y2 = fmaf(d, y1, x2);
        float y3 = fmaf(d, y2, x3);

        // A_t = sum y^2 ; B_t = y0 d + y1 d^2 + y2 d^3 + y3 d^4 (Horner)
        float At = fmaf(y3, y3, fmaf(y2, y2, fmaf(y1, y1, y0 * y0)));
        float Bt = d * fmaf(d, fmaf(d, fmaf(d, y3, y2), y1), y0);

        // warp inclusive scan of chunk totals, weight D4
        float sI = y3;
        float w  = D4;
        #pragma unroll
        for (int off = 1; off < 32; off <<= 1) {
            float up = __shfl_up_sync(0xffffffffu, sI, off);
            if (lane >= off) sI = fmaf(w, up, sI);
            w *= w;
        }
        float E = __shfl_up_sync(0xffffffffu, sI, 1);
        if (lane == 0) E = 0.0f;

        // true carry into this thread's chunk
        float c = fmaf(cj, Dl4, E);

        // chunk contribution: At + 2cBt + c^2 C4
        contrib += fmaf(c, fmaf(c, C4, Bt + Bt), At);

        // segment B-moment: KD * (Bt + E*C4)
        BwAcc = fmaf(KD, fmaf(E, C4, Bt), BwAcc);
        W     = fmaf(K, cj, W);

        // serial iteration-carry update
        float Tj = __shfl_sync(0xffffffffu, sI, 31);
        cj = fmaf(D128, cj, Tj);
        K  *= D128;
        KD *= D128;
    }

    // ---- per-warp reduce of contrib and BwAcc ----
    #pragma unroll
    for (int off = 16; off > 0; off >>= 1) {
        contrib += __shfl_down_sync(0xffffffffu, contrib, off);
        BwAcc   += __shfl_down_sync(0xffffffffu, BwAcc, off);
    }
    if (lane == 0) {
        warpA[warp] = contrib;
        warpB[warp] = fmaf(C128, W, BwAcc);  // + carry-induced B terms
        warpT[warp] = cj;                    // segment-final value
    }
    __syncthreads();

    // ---- tid0: chain warp segments, accumulate row total ----
    if (tid == 0) {
        float g = 0.0f, tot = 0.0f;
        #pragma unroll
        for (int v = 0; v < NWARPS; v++) {
            // segment contribution with carry-in g: A + 2gB + g^2 CBIG
            tot += fmaf(g, fmaf(g, CBIG, 2.0f * warpB[v]), warpA[v]);
            g = fmaf(D4096, g, warpT[v]);
        }
        g_partials[row] = tot;
        __threadfence();
        unsigned int t = atomicAdd(&g_ticket, 1u);
        isLast = (t == NROWS - 1);
    }
    __syncthreads();

    // ---- last block: fixed-order global reduce (deterministic) ----
    if (isLast) {
        __threadfence();
        float v = 0.0f;
        #pragma unroll
        for (int j = 0; j < NROWS / THREADS; j++)
            v += ((volatile float*)g_partials)[tid + j * THREADS];

        #pragma unroll
        for (int off = 16; off > 0; off >>= 1)
            v += __shfl_down_sync(0xffffffffu, v, off);
        if (lane == 0) wsum[warp] = v;
        __syncthreads();
        if (warp == 0) {
            float t2 = (lane < NWARPS) ? wsum[lane] : 0.0f;
            #pragma unroll
            for (int off = 2; off > 0; off >>= 1)
                t2 += __shfl_down_sync(0xffffffffu, t2, off);
            if (lane == 0) {
                out[0] = sqrtf(t2 * 0.05f);   // sqrt(sum / TAU * DT)
                g_ticket = 0;                 // reset for next graph replay
            }
        }
    }
}

extern "C" void kernel_launch(void* const* d_in, const int* in_sizes, int n_in,
                              void* d_out, int out_size)
{
    const float* inp = (const float*)d_in[0];
    const float* tgt = (const float*)d_in[1];
    float* out = (float*)d_out;

    vr_kernel<<<NROWS, THREADS>>>(inp, tgt, out);
}